// round 15
// baseline (speedup 1.0000x reference)
#include <cuda_runtime.h>
#include <cuda_fp16.h>
#include <cstdint>

#define DINLINE __device__ __forceinline__

// ---------------- problem constants ----------------
// B=4, H=16, S=2048, D=64.
static constexpr int S_LEN  = 2048;
static constexpr int D_DIM  = 64;
static constexpr int NHEADS = 64;                     // B*H
static constexpr int ELEMS  = NHEADS * S_LEN * D_DIM; // 8388608 per tensor

static constexpr int QTILE  = 256;
static constexpr int KTILE  = 64;
static constexpr int NKT    = S_LEN / KTILE;   // 32
static constexpr int NWARP  = 16;
static constexpr int NTHR   = NWARP * 32;      // 512

// SMEM: K/V ring of 4 stages + separate Q area.
// Rows stride 72 halves = 144 B (conflict-free for ldmatrix).
static constexpr int STRIDE   = 72;            // halves
static constexpr int ROW_B    = STRIDE * 2;    // 144 bytes
static constexpr int TILE_B   = KTILE * ROW_B; // 9216 bytes (one 64x64 f16 tile)
static constexpr int STAGE_B  = 2 * TILE_B;    // K + V: 18432
static constexpr int NSTAGE   = 4;
static constexpr int Q_OFF    = NSTAGE * STAGE_B;        // 73728
static constexpr int Q_B      = QTILE * ROW_B;           // 36864
static constexpr int SMEM_BYTES = Q_OFF + Q_B;           // 110592

// ---------------- f16 scratch (pre-converted inputs) ----------------
__device__ __half g_qh[ELEMS];   // pre-scaled by 1/16
__device__ __half g_kh[ELEMS];
__device__ __half g_vh[ELEMS];

// ---------------- helpers ----------------

DINLINE uint32_t smem_u32(const void* p) {
    uint32_t a;
    asm("{ .reg .u64 t; cvta.to.shared.u64 t, %1; cvt.u32.u64 %0, t; }"
        : "=r"(a) : "l"(p));
    return a;
}

DINLINE void cp16(uint32_t smem_dst, const void* gmem_src) {
    asm volatile("cp.async.cg.shared.global [%0], [%1], 16;"
                 :: "r"(smem_dst), "l"(gmem_src) : "memory");
}
DINLINE void cp_commit() { asm volatile("cp.async.commit_group;" ::: "memory"); }
DINLINE void cp_wait2()  { asm volatile("cp.async.wait_group 2;" ::: "memory"); }

DINLINE void ldsm_x4(uint32_t& r0, uint32_t& r1, uint32_t& r2, uint32_t& r3,
                     uint32_t addr) {
    asm volatile("ldmatrix.sync.aligned.m8n8.x4.shared.b16 {%0,%1,%2,%3}, [%4];"
                 : "=r"(r0), "=r"(r1), "=r"(r2), "=r"(r3) : "r"(addr));
}

DINLINE void ldsm_x4_trans(uint32_t& r0, uint32_t& r1, uint32_t& r2, uint32_t& r3,
                           uint32_t addr) {
    asm volatile("ldmatrix.sync.aligned.m8n8.x4.trans.shared.b16 {%0,%1,%2,%3}, [%4];"
                 : "=r"(r0), "=r"(r1), "=r"(r2), "=r"(r3) : "r"(addr));
}

// fp32-accumulator HMMA (PV GEMM)
DINLINE void mma16816(float* c, const uint32_t* a, uint32_t b0, uint32_t b1) {
    asm volatile(
        "mma.sync.aligned.m16n8k16.row.col.f32.f16.f16.f32 "
        "{%0,%1,%2,%3}, {%4,%5,%6,%7}, {%8,%9}, {%0,%1,%2,%3};"
        : "+f"(c[0]), "+f"(c[1]), "+f"(c[2]), "+f"(c[3])
        : "r"(a[0]), "r"(a[1]), "r"(a[2]), "r"(a[3]), "r"(b0), "r"(b1));
}

// f16-accumulator HMMA (QK GEMM): C-frag packing == PV A-frag layout.
DINLINE void mma16816_h(uint32_t* c, const uint32_t* a, uint32_t b0, uint32_t b1) {
    asm volatile(
        "mma.sync.aligned.m16n8k16.row.col.f16.f16.f16.f16 "
        "{%0,%1}, {%2,%3,%4,%5}, {%6,%7}, {%0,%1};"
        : "+r"(c[0]), "+r"(c[1])
        : "r"(a[0]), "r"(a[1]), "r"(a[2]), "r"(a[3]), "r"(b0), "r"(b1));
}

// sigmoid(score/8) on packed f16x2 of (score/16): 0.5 + 0.5*tanh(u)
DINLINE uint32_t sigmoid_h2(uint32_t u) {
    uint32_t t, r;
    const uint32_t H05 = 0x38003800u;  // (0.5, 0.5) f16x2
    asm("tanh.approx.f16x2 %0, %1;" : "=r"(t) : "r"(u));
    asm("fma.rn.f16x2 %0, %1, %2, %2;" : "=r"(r) : "r"(t), "r"(H05));
    return r;
}

// ---------------- pre-convert kernel: fp32 -> f16 scratch ----------------
__global__ void __launch_bounds__(256) convert_kernel(
    const float* __restrict__ gq, const float* __restrict__ gk,
    const float* __restrict__ gv)
{
    const int i = (blockIdx.x * 256 + threadIdx.x) * 4;
    const int which = blockIdx.y;
    const float* src = (which == 0) ? gq : (which == 1) ? gk : gv;
    __half*      dst = (which == 0) ? g_qh : (which == 1) ? g_kh : g_vh;
    const float sc = (which == 0) ? 0.0625f : 1.0f;  // fold sdpa/8 and tanh/2 into Q
    float4 f = *reinterpret_cast<const float4*>(src + i);
    __half2 h0 = __floats2half2_rn(f.x * sc, f.y * sc);
    __half2 h1 = __floats2half2_rn(f.z * sc, f.w * sc);
    uint2 u = make_uint2(*reinterpret_cast<uint32_t*>(&h0),
                         *reinterpret_cast<uint32_t*>(&h1));
    *reinterpret_cast<uint2*>(dst + i) = u;
}

// ---------------- main attention kernel ----------------
__global__ void __launch_bounds__(NTHR, 1) sigattn_kernel(float* __restrict__ gout)
{
    extern __shared__ char smem[];
    const uint32_t sb = smem_u32(smem);
    const int tid  = threadIdx.x;
    const int wid  = tid >> 5;
    const int lane = tid & 31;

    const int bx = blockIdx.x;
    const int qt = bx & 7;           // q-tile within head
    const int bh = bx >> 3;          // flattened (b,h)
    const size_t head_base = (size_t)bh * S_LEN * D_DIM;
    const __half* qh = g_qh + head_base + (size_t)qt * QTILE * D_DIM;
    const __half* kh = g_kh + head_base;
    const __half* vh = g_vh + head_base;
    float*        ob = gout + head_base + (size_t)qt * QTILE * D_DIM;

    // per-thread K/V staging coords: one 16B cp.async each for K and V
    const int kvrow = tid >> 3;             // 0..63
    const int c8    = tid & 7;              // 16B chunk within 128B row
    const uint32_t kv_doff = (uint32_t)(kvrow * ROW_B + c8 * 16);
    const size_t   kv_goff = (size_t)kvrow * D_DIM + c8 * 8;

    // ---- prologue: kick off K/V tiles 0..2 into stages 0..2 ----
    #pragma unroll
    for (int p = 0; p < NSTAGE - 1; p++) {
        uint32_t stg = sb + (uint32_t)(p * STAGE_B);
        cp16(stg + kv_doff,          kh + (size_t)p * KTILE * D_DIM + kv_goff);
        cp16(stg + TILE_B + kv_doff, vh + (size_t)p * KTILE * D_DIM + kv_goff);
        cp_commit();
    }

    // ---- stage Q (already f16, pre-scaled) into its own SMEM area ----
    {
        int row  = tid >> 1;                // 0..255
        int half = tid & 1;                 // 0/1 -> 64B
        const uint4* src = reinterpret_cast<const uint4*>(qh + (size_t)row * D_DIM + half * 32);
        uint4* dst = reinterpret_cast<uint4*>(smem + Q_OFF + row * ROW_B + half * 64);
        dst[0] = src[0]; dst[1] = src[1]; dst[2] = src[2]; dst[3] = src[3];
    }
    __syncthreads();

    const int idx = lane & 15;
    const int seg = lane >> 4;          // 0/1
    const int rot = (wid >> 2) & 3;     // chunk rotation: varies WITHIN each SMSP

    // Q fragments: qf[kstep][4] regs, warp rows 16*wid .. +15
    uint32_t qf[4][4];
    #pragma unroll
    for (int s = 0; s < 4; s++) {
        uint32_t addr = sb + Q_OFF +
            (uint32_t)((16 * wid + idx) * ROW_B + (16 * s + 8 * seg) * 2);
        ldsm_x4(qf[s][0], qf[s][1], qf[s][2], qf[s][3], addr);
    }

    // ---- O accumulators: 8 d-tiles x 4 fp32 ----
    float oc[8][4];
    #pragma unroll
    for (int j = 0; j < 8; j++)
        #pragma unroll
        for (int r = 0; r < 4; r++) oc[j][r] = 0.0f;

    // loop-invariant piece of B-side ldmatrix addresses (byte units)
    const uint32_t lds_base = sb + (uint32_t)(idx * ROW_B + 16 * seg);

    for (int kt = 0; kt < NKT; kt++) {
        // tile kt landed (own copies), then make all threads' copies visible
        cp_wait2();
        __syncthreads();

        // issue tile kt+3 into stage (kt+3)%4 (readers of that stage finished
        // in iter kt-1, guaranteed by the barrier above). Always commit to
        // keep the group count invariant.
        if (kt + 3 < NKT) {
            uint32_t stg = sb + (uint32_t)(((kt + 3) & 3) * STAGE_B);
            cp16(stg + kv_doff,          kh + (size_t)(kt + 3) * KTILE * D_DIM + kv_goff);
            cp16(stg + TILE_B + kv_doff, vh + (size_t)(kt + 3) * KTILE * D_DIM + kv_goff);
        }
        cp_commit();

        const uint32_t cur_off = (uint32_t)((kt & 3) * STAGE_B);

        // ---- compute, 16-key chunks in per-warp rotated order ----
        #pragma unroll
        for (int tc = 0; tc < 4; tc++) {
            const int t = (tc + rot) & 3;

            // QK for keys 16t..16t+15 (f16 accumulators)
            uint32_t sch0[2] = {0u, 0u};    // keys lo8
            uint32_t sch1[2] = {0u, 0u};    // keys hi8
            #pragma unroll
            for (int s = 0; s < 4; s++) {
                uint32_t r0, r1, r2, r3;
                uint32_t addr = lds_base + cur_off +
                    (uint32_t)(16 * t * ROW_B + 32 * s);
                ldsm_x4(r0, r1, r2, r3, addr);
                mma16816_h(sch0, qf[s], r0, r2);
                mma16816_h(sch1, qf[s], r1, r3);
            }

            // V fragments issued before the MUFU chain (latency hiding)
            uint32_t vf[4][4];
            #pragma unroll
            for (int m = 0; m < 4; m++) {
                uint32_t addr = lds_base + cur_off + (uint32_t)TILE_B +
                    (uint32_t)(16 * t * ROW_B + 32 * m);
                ldsm_x4_trans(vf[m][0], vf[m][1], vf[m][2], vf[m][3], addr);
            }

            // sigmoid (f16x2) -> P A-frag directly (no repack)
            uint32_t pf[4];
            pf[0] = sigmoid_h2(sch0[0]);
            pf[1] = sigmoid_h2(sch0[1]);
            pf[2] = sigmoid_h2(sch1[0]);
            pf[3] = sigmoid_h2(sch1[1]);

            // PV: O += P(:,chunk) @ V(chunk,:)  (fp32 accum)
            #pragma unroll
            for (int m = 0; m < 4; m++) {
                mma16816(oc[2 * m],     pf, vf[m][0], vf[m][1]);
                mma16816(oc[2 * m + 1], pf, vf[m][2], vf[m][3]);
            }
        }
    }

    // ---- epilogue: write O (fp32) ----
    {
        const int g  = lane >> 2;
        const int tg = lane & 3;
        const int r0 = 16 * wid + g;
        const int r1 = r0 + 8;
        #pragma unroll
        for (int j = 0; j < 8; j++) {
            int c = 8 * j + 2 * tg;
            *reinterpret_cast<float2*>(ob + (size_t)r0 * D_DIM + c) =
                make_float2(oc[j][0], oc[j][1]);
            *reinterpret_cast<float2*>(ob + (size_t)r1 * D_DIM + c) =
                make_float2(oc[j][2], oc[j][3]);
        }
    }
}

extern "C" void kernel_launch(void* const* d_in, const int* in_sizes, int n_in,
                              void* d_out, int out_size) {
    (void)in_sizes; (void)n_in; (void)out_size;
    const float* q = (const float*)d_in[0];
    const float* k = (const float*)d_in[1];
    const float* v = (const float*)d_in[2];
    float* out = (float*)d_out;

    // 1) fp32 -> f16 pre-convert (Q pre-scaled by 1/16)
    dim3 cgrid(ELEMS / (256 * 4), 3);
    convert_kernel<<<cgrid, 256>>>(q, k, v);

    // 2) attention on f16 inputs
    cudaFuncSetAttribute(sigattn_kernel,
                         cudaFuncAttributeMaxDynamicSharedMemorySize, SMEM_BYTES);
    sigattn_kernel<<<512, NTHR, SMEM_BYTES>>>(out);
}

// round 17
// speedup vs baseline: 1.0076x; 1.0076x over previous
#include <cuda_runtime.h>
#include <cuda_fp16.h>
#include <cstdint>

#define DINLINE __device__ __forceinline__

// ---------------- problem constants ----------------
// B=4, H=16, S=2048, D=64.
static constexpr int S_LEN  = 2048;
static constexpr int D_DIM  = 64;
static constexpr int NHEADS = 64;                     // B*H
static constexpr int ELEMS  = NHEADS * S_LEN * D_DIM; // 8388608 per tensor

static constexpr int QTILE  = 256;
static constexpr int KTILE  = 128;
static constexpr int NKT    = S_LEN / KTILE;   // 16
static constexpr int NCHUNK = KTILE / 16;      // 8
static constexpr int NWARP  = 16;
static constexpr int NTHR   = NWARP * 32;      // 512

// SMEM: K/V ring of 3 stages + separate Q area.
// Rows stride 72 halves = 144 B (conflict-free for ldmatrix).
static constexpr int STRIDE   = 72;            // halves
static constexpr int ROW_B    = STRIDE * 2;    // 144 bytes
static constexpr int TILE_B   = KTILE * ROW_B; // 18432 bytes (one 128x64 f16 tile)
static constexpr int STAGE_B  = 2 * TILE_B;    // K + V: 36864
static constexpr int NSTAGE   = 3;
static constexpr int Q_OFF    = NSTAGE * STAGE_B;        // 110592
static constexpr int Q_B      = QTILE * ROW_B;           // 36864
static constexpr int SMEM_BYTES = Q_OFF + Q_B;           // 147456

// ---------------- f16 scratch (pre-converted K/V) ----------------
__device__ __half g_kh[ELEMS];
__device__ __half g_vh[ELEMS];

// ---------------- helpers ----------------

DINLINE uint32_t smem_u32(const void* p) {
    uint32_t a;
    asm("{ .reg .u64 t; cvta.to.shared.u64 t, %1; cvt.u32.u64 %0, t; }"
        : "=r"(a) : "l"(p));
    return a;
}

DINLINE void cp16(uint32_t smem_dst, const void* gmem_src) {
    asm volatile("cp.async.cg.shared.global [%0], [%1], 16;"
                 :: "r"(smem_dst), "l"(gmem_src) : "memory");
}
DINLINE void cp_commit() { asm volatile("cp.async.commit_group;" ::: "memory"); }
DINLINE void cp_wait1()  { asm volatile("cp.async.wait_group 1;" ::: "memory"); }

DINLINE void ldsm_x4(uint32_t& r0, uint32_t& r1, uint32_t& r2, uint32_t& r3,
                     uint32_t addr) {
    asm volatile("ldmatrix.sync.aligned.m8n8.x4.shared.b16 {%0,%1,%2,%3}, [%4];"
                 : "=r"(r0), "=r"(r1), "=r"(r2), "=r"(r3) : "r"(addr));
}

DINLINE void ldsm_x4_trans(uint32_t& r0, uint32_t& r1, uint32_t& r2, uint32_t& r3,
                           uint32_t addr) {
    asm volatile("ldmatrix.sync.aligned.m8n8.x4.trans.shared.b16 {%0,%1,%2,%3}, [%4];"
                 : "=r"(r0), "=r"(r1), "=r"(r2), "=r"(r3) : "r"(addr));
}

// fp32-accumulator HMMA (PV GEMM)
DINLINE void mma16816(float* c, const uint32_t* a, uint32_t b0, uint32_t b1) {
    asm volatile(
        "mma.sync.aligned.m16n8k16.row.col.f32.f16.f16.f32 "
        "{%0,%1,%2,%3}, {%4,%5,%6,%7}, {%8,%9}, {%0,%1,%2,%3};"
        : "+f"(c[0]), "+f"(c[1]), "+f"(c[2]), "+f"(c[3])
        : "r"(a[0]), "r"(a[1]), "r"(a[2]), "r"(a[3]), "r"(b0), "r"(b1));
}

// f16-accumulator HMMA (QK GEMM): C-frag packing == PV A-frag layout.
DINLINE void mma16816_h(uint32_t* c, const uint32_t* a, uint32_t b0, uint32_t b1) {
    asm volatile(
        "mma.sync.aligned.m16n8k16.row.col.f16.f16.f16.f16 "
        "{%0,%1}, {%2,%3,%4,%5}, {%6,%7}, {%0,%1};"
        : "+r"(c[0]), "+r"(c[1])
        : "r"(a[0]), "r"(a[1]), "r"(a[2]), "r"(a[3]), "r"(b0), "r"(b1));
}

// sigmoid(score/8) on packed f16x2 of (score/16): 0.5 + 0.5*tanh(u)
DINLINE uint32_t sigmoid_h2(uint32_t u) {
    uint32_t t, r;
    const uint32_t H05 = 0x38003800u;  // (0.5, 0.5) f16x2
    asm("tanh.approx.f16x2 %0, %1;" : "=r"(t) : "r"(u));
    asm("fma.rn.f16x2 %0, %1, %2, %2;" : "=r"(r) : "r"(t), "r"(H05));
    return r;
}

DINLINE uint32_t packh2(float a, float b) {
    __half2 h = __floats2half2_rn(a, b);
    return *reinterpret_cast<uint32_t*>(&h);
}

// ---------------- pre-convert kernel: fp32 -> f16 (K and V only) ----------------
__global__ void __launch_bounds__(256) convert_kernel(
    const float* __restrict__ gk, const float* __restrict__ gv)
{
    const int i = (blockIdx.x * 256 + threadIdx.x) * 4;
    const float* src = (blockIdx.y == 0) ? gk : gv;
    __half*      dst = (blockIdx.y == 0) ? g_kh : g_vh;
    float4 f = *reinterpret_cast<const float4*>(src + i);
    __half2 h0 = __floats2half2_rn(f.x, f.y);
    __half2 h1 = __floats2half2_rn(f.z, f.w);
    uint2 u = make_uint2(*reinterpret_cast<uint32_t*>(&h0),
                         *reinterpret_cast<uint32_t*>(&h1));
    *reinterpret_cast<uint2*>(dst + i) = u;
}

// ---------------- main attention kernel ----------------
__global__ void __launch_bounds__(NTHR, 1) sigattn_kernel(
    const float* __restrict__ gq, float* __restrict__ gout)
{
    extern __shared__ char smem[];
    const uint32_t sb = smem_u32(smem);
    const int tid  = threadIdx.x;
    const int wid  = tid >> 5;
    const int lane = tid & 31;

    const int bx = blockIdx.x;
    const int qt = bx & 7;           // q-tile within head
    const int bh = bx >> 3;          // flattened (b,h)
    const size_t head_base = (size_t)bh * S_LEN * D_DIM;
    const float*  qb = gq   + head_base + (size_t)qt * QTILE * D_DIM;
    const __half* kh = g_kh + head_base;
    const __half* vh = g_vh + head_base;
    float*        ob = gout + head_base + (size_t)qt * QTILE * D_DIM;

    // per-thread K/V staging: two 16B cp.async each for K and V per tile
    // (128 rows x 128B per tile, 512 threads)
    const int kvrow = tid >> 2;             // 0..127
    const int cpair = (tid & 3) * 2;        // chunk pair: 0,2,4,6
    const uint32_t kv_doff = (uint32_t)(kvrow * ROW_B + cpair * 16);
    const size_t   kv_goff = (size_t)kvrow * D_DIM + cpair * 8;

    // ---- prologue: kick off K/V tiles 0..1 into stages 0..1 ----
    #pragma unroll
    for (int p = 0; p < NSTAGE - 1; p++) {
        uint32_t stg = sb + (uint32_t)(p * STAGE_B);
        const __half* kt_p = kh + (size_t)p * KTILE * D_DIM + kv_goff;
        const __half* vt_p = vh + (size_t)p * KTILE * D_DIM + kv_goff;
        cp16(stg + kv_doff,               kt_p);
        cp16(stg + kv_doff + 16,          kt_p + 8);
        cp16(stg + TILE_B + kv_doff,      vt_p);
        cp16(stg + TILE_B + kv_doff + 16, vt_p + 8);
        cp_commit();
    }

    // ---- stage Q (fp32 -> f16, pre-scaled by 1/16) into its own SMEM area ----
    {
        const float SC = 0.0625f;           // folds sdpa/8 and tanh/2
        int row = tid >> 1;                 // 0..255
        int c0  = (tid & 1) * 32;           // 0 or 32
        const float4* src = reinterpret_cast<const float4*>(qb + (size_t)row * D_DIM + c0);
        uint32_t* dst = reinterpret_cast<uint32_t*>(smem + Q_OFF + row * ROW_B + c0 * 2);
        #pragma unroll
        for (int i = 0; i < 8; i++) {
            float4 f = src[i];
            dst[2 * i]     = packh2(f.x * SC, f.y * SC);
            dst[2 * i + 1] = packh2(f.z * SC, f.w * SC);
        }
    }
    __syncthreads();

    const int idx = lane & 15;
    const int seg = lane >> 4;              // 0/1
    const int rot = ((wid >> 2) & 3) << 1;  // 0,2,4,6: varies WITHIN each SMSP

    // Q fragments: qf[kstep][4] regs, warp rows 16*wid .. +15
    uint32_t qf[4][4];
    #pragma unroll
    for (int s = 0; s < 4; s++) {
        uint32_t addr = sb + Q_OFF +
            (uint32_t)((16 * wid + idx) * ROW_B + (16 * s + 8 * seg) * 2);
        ldsm_x4(qf[s][0], qf[s][1], qf[s][2], qf[s][3], addr);
    }

    // ---- O accumulators: 8 d-tiles x 4 fp32 ----
    float oc[8][4];
    #pragma unroll
    for (int j = 0; j < 8; j++)
        #pragma unroll
        for (int r = 0; r < 4; r++) oc[j][r] = 0.0f;

    // loop-invariant piece of B-side ldmatrix addresses (byte units)
    const uint32_t lds_base = sb + (uint32_t)(idx * ROW_B + 16 * seg);

    for (int kt = 0; kt < NKT; kt++) {
        // tile kt landed (own copies); barrier makes all threads' copies visible
        cp_wait1();
        __syncthreads();

        // issue tile kt+2 into stage (kt+2)%3 (readers finished in iter kt-1,
        // guaranteed by the barrier above). Always commit to keep counts fixed.
        if (kt + 2 < NKT) {
            uint32_t stg = sb + (uint32_t)(((kt + 2) % 3) * STAGE_B);
            const __half* kt_p = kh + (size_t)(kt + 2) * KTILE * D_DIM + kv_goff;
            const __half* vt_p = vh + (size_t)(kt + 2) * KTILE * D_DIM + kv_goff;
            cp16(stg + kv_doff,               kt_p);
            cp16(stg + kv_doff + 16,          kt_p + 8);
            cp16(stg + TILE_B + kv_doff,      vt_p);
            cp16(stg + TILE_B + kv_doff + 16, vt_p + 8);
        }
        cp_commit();

        const uint32_t cur_off = (uint32_t)((kt % 3) * STAGE_B);

        // ---- compute, 16-key chunks in per-warp rotated order ----
        #pragma unroll
        for (int tc = 0; tc < NCHUNK; tc++) {
            const int t = (tc + rot) & 7;

            // QK for keys 16t..16t+15 (f16 accumulators)
            uint32_t sch0[2] = {0u, 0u};    // keys lo8
            uint32_t sch1[2] = {0u, 0u};    // keys hi8
            #pragma unroll
            for (int s = 0; s < 4; s++) {
                uint32_t r0, r1, r2, r3;
                uint32_t addr = lds_base + cur_off +
                    (uint32_t)(16 * t * ROW_B + 32 * s);
                ldsm_x4(r0, r1, r2, r3, addr);
                mma16816_h(sch0, qf[s], r0, r2);
                mma16816_h(sch1, qf[s], r1, r3);
            }

            // V fragments issued before the MUFU chain (latency hiding)
            uint32_t vf[4][4];
            #pragma unroll
            for (int m = 0; m < 4; m++) {
                uint32_t addr = lds_base + cur_off + (uint32_t)TILE_B +
                    (uint32_t)(16 * t * ROW_B + 32 * m);
                ldsm_x4_trans(vf[m][0], vf[m][1], vf[m][2], vf[m][3], addr);
            }

            // sigmoid (f16x2) -> P A-frag directly (no repack)
            uint32_t pf[4];
            pf[0] = sigmoid_h2(sch0[0]);
            pf[1] = sigmoid_h2(sch0[1]);
            pf[2] = sigmoid_h2(sch1[0]);
            pf[3] = sigmoid_h2(sch1[1]);

            // PV: O += P(:,chunk) @ V(chunk,:)  (fp32 accum)
            #pragma unroll
            for (int m = 0; m < 4; m++) {
                mma16816(oc[2 * m],     pf, vf[m][0], vf[m][1]);
                mma16816(oc[2 * m + 1], pf, vf[m][2], vf[m][3]);
            }
        }
    }

    // ---- epilogue: write O (fp32) ----
    {
        const int g  = lane >> 2;
        const int tg = lane & 3;
        const int r0 = 16 * wid + g;
        const int r1 = r0 + 8;
        #pragma unroll
        for (int j = 0; j < 8; j++) {
            int c = 8 * j + 2 * tg;
            *reinterpret_cast<float2*>(ob + (size_t)r0 * D_DIM + c) =
                make_float2(oc[j][0], oc[j][1]);
            *reinterpret_cast<float2*>(ob + (size_t)r1 * D_DIM + c) =
                make_float2(oc[j][2], oc[j][3]);
        }
    }
}

extern "C" void kernel_launch(void* const* d_in, const int* in_sizes, int n_in,
                              void* d_out, int out_size) {
    (void)in_sizes; (void)n_in; (void)out_size;
    const float* q = (const float*)d_in[0];
    const float* k = (const float*)d_in[1];
    const float* v = (const float*)d_in[2];
    float* out = (float*)d_out;

    // 1) fp32 -> f16 pre-convert for K and V (Q converts inline in main kernel)
    dim3 cgrid(ELEMS / (256 * 4), 2);
    convert_kernel<<<cgrid, 256>>>(k, v);

    // 2) attention
    cudaFuncSetAttribute(sigattn_kernel,
                         cudaFuncAttributeMaxDynamicSharedMemorySize, SMEM_BYTES);
    sigattn_kernel<<<512, NTHR, SMEM_BYTES>>>(q, out);
}